// round 13
// baseline (speedup 1.0000x reference)
#include <cuda_runtime.h>
#include <cstdint>

// out[n,c,oh,ow] = x[n,c,2*oh,2*ow]
//   x:   (8,128,512,512) fp32, contiguous NCHW  -> 268,435,456 elems
//   out: (8,128,256,256) fp32                    ->  67,108,864 elems
//
// One WARP per output row. Lane k loads contiguous float4 irow[k + 32*j]
// (j=0..3) — fully coalesced, dense 512B per warp per LDG. The even
// elements (.x,.z) of lane k's float4 are exactly output floats 2k,2k+1
// = output float2 index k: deinterleave is free, no shuffles. 4
// independent front-batched loads, 4 coalesced STG.64.
//
// 1024-thread blocks: 8192 CTAs, each reading a 128KB contiguous input
// span — maximizes DRAM page-hit locality per SM (the 256->512 thread
// step moved DRAM duty 86.8%->87.9%; this extends the same mechanism).
// Measured at the HBM roofline (~7 TB/s); residual vs spec is R/W
// turnaround on the 2:1 mixed stream, not kernel-addressable.

static constexpr int OUT_ROWS   = 8 * 128 * 256;  // 262,144 output rows
static constexpr int IN_ROW_F4  = 128;            // float4 per input row
static constexpr int OUT_ROW_F2 = 128;            // float2 per output row
static constexpr int THREADS    = 1024;           // 32 warps per block
static constexpr int WARPS_PER_BLOCK = THREADS / 32;

__global__ __launch_bounds__(THREADS) void strided_slice_kernel(
    const float4* __restrict__ in, float2* __restrict__ out)
{
    int gwarp = (blockIdx.x * blockDim.x + threadIdx.x) >> 5;  // output row r
    int lane  = threadIdx.x & 31;

    // input row 2*r starts at float4 index (2*r)*128
    const float4* irow = in  + (long)gwarp * (2 * IN_ROW_F4);
    float2*       orow = out + (long)gwarp * OUT_ROW_F2;

    // 4 independent, warp-contiguous 128-bit streaming loads
    float4 a = __ldcs(irow + lane);
    float4 b = __ldcs(irow + lane + 32);
    float4 c = __ldcs(irow + lane + 64);
    float4 d = __ldcs(irow + lane + 96);

    // even elements -> output float2 at the same lane index: free deinterleave
    __stcs(orow + lane,      make_float2(a.x, a.z));
    __stcs(orow + lane + 32, make_float2(b.x, b.z));
    __stcs(orow + lane + 64, make_float2(c.x, c.z));
    __stcs(orow + lane + 96, make_float2(d.x, d.z));
}

extern "C" void kernel_launch(void* const* d_in, const int* in_sizes, int n_in,
                              void* d_out, int out_size)
{
    const float4* in  = (const float4*)d_in[0];
    float2*       out = (float2*)d_out;

    int blocks = OUT_ROWS / WARPS_PER_BLOCK;  // 8,192 blocks x 1024 threads
    strided_slice_kernel<<<blocks, THREADS>>>(in, out);
}